// round 16
// baseline (speedup 1.0000x reference)
#include <cuda_runtime.h>

typedef unsigned int u32;
typedef unsigned long long u64;

// xin[800,100] = x[800,460800] @ w_in[100,460800]^T computed EXACTLY via int8
// tensor cores: 4-limb balanced base-128 quantization of both operands
// (x to 2^-25, w to 2^-28), 10 integer product groups (i+j<=3) accumulated in
// s32 (no rounding), combined in fp64. Error ~1e-6 (omitted 2^-39-weight terms
// + tiny-element residuals). Kills the bf16-TC RZ-chain noise that failed
// R11/R15. Then deterministic split-K fp64 reduce + LIF/LI scan.

#define F_K    460800L
#define NCHUNK 14400        // k chunks of 32
#define SPLITS 11
#define CPS    1310         // chunks per split (last split: 1300)
#define MT     64
#define NRT    13           // 13*64 = 832 >= 800
#define NCOLP  112
#define NTHREADS 256

// smem stage: X planes 4*(64*48) + W planes 4*(112*48)
#define XPL    3072
#define WOFF   12288
#define WPL    5376
#define STAGE  33792
#define SMEM_TOTAL (2 * STAGE)   // 67584

// W limb planes, chunk-tiled: word idx = c*3584 + p*896 + row*8 + q
__device__ __align__(16) u32 g_wl[(long)NCHUNK * 3584];   // 206.4 MB
__device__ float g_part[SPLITS * 800 * NCOLP];            // 3.9 MB
__device__ float g_xin[800 * 100];

__device__ __forceinline__ u32 smem_u32(const void* p) {
    u32 a;
    asm("{ .reg .u64 t; cvta.to.shared.u64 t, %1; cvt.u32.u64 %0, t; }" : "=r"(a) : "l"(p));
    return a;
}
__device__ __forceinline__ float rnif(float x) {
    float r; asm("cvt.rni.f32.f32 %0, %1;" : "=f"(r) : "f"(x)); return r;
}
__device__ __forceinline__ u32 prmt(u32 a, u32 b, u32 s) {
    u32 d; asm("prmt.b32 %0, %1, %2, %3;" : "=r"(d) : "r"(a), "r"(b), "r"(s)); return d;
}
__device__ __forceinline__ u32 lds32(u32 a) {
    u32 d; asm volatile("ld.shared.b32 %0, [%1];" : "=r"(d) : "r"(a)); return d;
}
__device__ __forceinline__ void mma_s8(int* c, const u32* a, u32 b0, u32 b1) {
    asm volatile(
        "mma.sync.aligned.m16n8k32.row.col.s32.s8.s8.s32 "
        "{%0,%1,%2,%3},{%4,%5,%6,%7},{%8,%9},{%0,%1,%2,%3};"
        : "+r"(c[0]), "+r"(c[1]), "+r"(c[2]), "+r"(c[3])
        : "r"(a[0]), "r"(a[1]), "r"(a[2]), "r"(a[3]), "r"(b0), "r"(b1));
}

// 4 balanced base-128 limbs of each of 4 floats, packed per-plane (byte e = elem e).
// limb0 = rni(v*s0); residual chain exact (Veltkamp-style with rni + exact fma).
__device__ __forceinline__ void limbs_pack(float4 v, float s0, u32 pk[4]) {
    float in[4] = {v.x, v.y, v.z, v.w};
    u32 li[4][4];
    const float i0 = 1.f / s0;
    const float s1 = s0 * 128.f, i1 = i0 * 0.0078125f;
    const float s2 = s1 * 128.f, i2 = i1 * 0.0078125f;
    const float s3 = s2 * 128.f;
#pragma unroll
    for (int e = 0; e < 4; e++) {
        float x = in[e];
        float f0 = rnif(x * s0); float r = fmaf(f0, -i0, x);
        float f1 = rnif(r * s1); r = fmaf(f1, -i1, r);
        float f2 = rnif(r * s2); r = fmaf(f2, -i2, r);
        float f3 = rnif(r * s3);
        li[0][e] = (u32)__float2int_rn(f0);
        li[1][e] = (u32)__float2int_rn(f1);
        li[2][e] = (u32)__float2int_rn(f2);
        li[3][e] = (u32)__float2int_rn(f3);
    }
#pragma unroll
    for (int p = 0; p < 4; p++) {
        u32 t01 = prmt(li[p][0], li[p][1], 0x0040);
        u32 t23 = prmt(li[p][2], li[p][3], 0x0040);
        pk[p] = prmt(t01, t23, 0x5410);
    }
}

// ---- kernel 1: convert W once to limb planes (rows 100..111 zero) ----
__global__ __launch_bounds__(128) void wconv(const float* __restrict__ W) {
    const int c = blockIdx.x, tid = threadIdx.x;
    for (int i = tid; i < 896; i += 128) {         // 112 rows x 8 quads
        int row = i >> 3, q = i & 7;
        u32 pk[4] = {0u, 0u, 0u, 0u};
        if (row < 100) {
            float4 v = *(const float4*)(W + (long)row * F_K + (long)c * 32 + q * 4);
            limbs_pack(v, 128.f, pk);              // w scale 2^7 (|w| <= ~0.9)
        }
        long wi = (long)c * 3584 + row * 8 + q;
#pragma unroll
        for (int p = 0; p < 4; p++) g_wl[wi + p * 896] = pk[p];
    }
}

// ---- kernel 2: exact s8 GEMM ----
__global__ __launch_bounds__(NTHREADS, 1) void gemm_s8(const float* __restrict__ X) {
    extern __shared__ __align__(16) char smem[];
    const u32 sb = smem_u32(smem);
    const int tid = threadIdx.x, lane = tid & 31, wid = tid >> 5;
    const int mw = wid & 3, nw = wid >> 2;         // 4 m-warps x 2 n-warps
    const int rt = blockIdx.x, sp = blockIdx.y;
    const int c0 = sp * CPS;
    const int ntiles = (sp == SPLITS - 1) ? (NCHUNK - c0) : CPS;

    int S[4][7][4];                                 // [group][ntile][frag] s32
#pragma unroll
    for (int g = 0; g < 4; g++)
#pragma unroll
        for (int t = 0; t < 7; t++)
#pragma unroll
            for (int j = 0; j < 4; j++) S[g][t][j] = 0;

    // X producer: 2 assignments/thread (64 rows x 8 quads)
    long xoff[2]; u32 xsts[2];
#pragma unroll
    for (int i = 0; i < 2; i++) {
        int a = tid + i * NTHREADS, r = a >> 3, q = a & 7;
        int row = min(rt * MT + r, 799);           // clamp (outputs masked)
        xoff[i] = (long)row * F_K + (long)c0 * 32 + q * 4;
        xsts[i] = r * 48 + q * 4;
    }
    // W copy: 16B chunks, dst offsets loop-invariant
    u32 wdst[4]; int widx[4];
#pragma unroll
    for (int j = 0; j < 4; j++) {
        int idx = tid + j * NTHREADS;              // < 896
        widx[j] = (idx < 896) ? idx : -1;
        int pl = idx / 224, rem = idx % 224, row = rem >> 1, h = rem & 1;
        wdst[j] = WOFF + pl * WPL + row * 48 + h * 16;
    }

    // ldmatrix-free fragment addresses
    const u32 a_base = (16 * mw + (lane >> 2)) * 48 + 4 * (lane & 3);
    const u32 b_base = WOFF + (56 * nw + (lane >> 2)) * 48 + 4 * (lane & 3);

    // prologue: stage 0
    float4 xr[2]; uint4 wr[4];
#pragma unroll
    for (int i = 0; i < 2; i++) xr[i] = *(const float4*)(X + xoff[i]);
#pragma unroll
    for (int j = 0; j < 4; j++)
        if (widx[j] >= 0) wr[j] = *(const uint4*)(g_wl + (long)c0 * 3584 + widx[j] * 4);
    {
        u32 pk[4];
#pragma unroll
        for (int i = 0; i < 2; i++) {
            limbs_pack(xr[i], 16.f, pk);           // x scale 2^4 (|x| <= ~6.5)
#pragma unroll
            for (int p = 0; p < 4; p++)
                *(u32*)(smem + xsts[i] + p * XPL) = pk[p];
        }
#pragma unroll
        for (int j = 0; j < 4; j++)
            if (widx[j] >= 0) *(uint4*)(smem + wdst[j]) = wr[j];
    }
    __syncthreads();

    for (int kt = 0; kt < ntiles; kt++) {
        const bool more = (kt + 1) < ntiles;
        if (more) {
            const long kb = (long)(kt + 1) * 32;
#pragma unroll
            for (int i = 0; i < 2; i++) xr[i] = *(const float4*)(X + xoff[i] + kb);
            const long wb = (long)(c0 + kt + 1) * 3584;
#pragma unroll
            for (int j = 0; j < 4; j++)
                if (widx[j] >= 0) wr[j] = *(const uint4*)(g_wl + wb + widx[j] * 4);
        }
        const u32 st = sb + (u32)(kt & 1) * STAGE;
        u32 a[4][4];
#pragma unroll
        for (int p = 0; p < 4; p++) {
            u32 ab = st + p * XPL + a_base;
            a[p][0] = lds32(ab);        a[p][1] = lds32(ab + 384);
            a[p][2] = lds32(ab + 16);   a[p][3] = lds32(ab + 400);
        }
#pragma unroll
        for (int tn = 0; tn < 7; tn++) {
            u32 b[4][2];
#pragma unroll
            for (int p = 0; p < 4; p++) {
                u32 bb = st + p * WPL + b_base + tn * (8 * 48);
                b[p][0] = lds32(bb); b[p][1] = lds32(bb + 16);
            }
            mma_s8(S[0][tn], a[0], b[0][0], b[0][1]);                 // g0: 00
            mma_s8(S[1][tn], a[0], b[1][0], b[1][1]);                 // g1: 01
            mma_s8(S[1][tn], a[1], b[0][0], b[0][1]);                 //     10
            mma_s8(S[2][tn], a[0], b[2][0], b[2][1]);                 // g2: 02
            mma_s8(S[2][tn], a[1], b[1][0], b[1][1]);                 //     11
            mma_s8(S[2][tn], a[2], b[0][0], b[0][1]);                 //     20
            mma_s8(S[3][tn], a[0], b[3][0], b[3][1]);                 // g3: 03
            mma_s8(S[3][tn], a[1], b[2][0], b[2][1]);                 //     12
            mma_s8(S[3][tn], a[2], b[1][0], b[1][1]);                 //     21
            mma_s8(S[3][tn], a[3], b[0][0], b[0][1]);                 //     30
        }
        if (more) {
            const u32 nxo = (u32)((kt + 1) & 1) * STAGE;
            u32 pk[4];
#pragma unroll
            for (int i = 0; i < 2; i++) {
                limbs_pack(xr[i], 16.f, pk);
#pragma unroll
                for (int p = 0; p < 4; p++)
                    *(u32*)(smem + nxo + xsts[i] + p * XPL) = pk[p];
            }
#pragma unroll
            for (int j = 0; j < 4; j++)
                if (widx[j] >= 0) *(uint4*)(smem + nxo + wdst[j]) = wr[j];
        }
        __syncthreads();
    }

    // epilogue: combine groups in fp64 (exact), store split partials
    // value = 2^-11 * (S0 + 2^-7*(S1 + 2^-7*(S2 + 2^-7*S3)))
    const int r0 = rt * MT + 16 * mw + (lane >> 2);
    const int colb = 56 * nw + 2 * (lane & 3);
#pragma unroll
    for (int tn = 0; tn < 7; tn++) {
        int col = colb + 8 * tn;
#pragma unroll
        for (int h = 0; h < 2; h++) {
            int row = r0 + 8 * h;
            if (row < 800) {
#pragma unroll
                for (int e = 0; e < 2; e++) {
                    double d = (double)S[3][tn][2 * h + e];
                    d = d * 0.0078125 + (double)S[2][tn][2 * h + e];
                    d = d * 0.0078125 + (double)S[1][tn][2 * h + e];
                    d = d * 0.0078125 + (double)S[0][tn][2 * h + e];
                    g_part[((long)sp * 800 + row) * NCOLP + col + e] =
                        (float)(d * 4.8828125e-4);
                }
            }
        }
    }
}

// ---- kernel 3: deterministic split-K reduce in fp64 ----
__global__ void reduce_kernel() {
    int row = blockIdx.x, c = threadIdx.x;
    if (c >= 100) return;
    double s = 0.0;
    for (int sp = 0; sp < SPLITS; sp++)
        s += (double)g_part[((long)sp * 800 + row) * NCOLP + c];
    g_xin[row * 100 + c] = (float)s;
}

// ---- kernel 4: per-batch LIF/LI scan (proven R4/R5) ----
__global__ __launch_bounds__(128) void scan_kernel(const float* __restrict__ wrec,
                                                   const float* __restrict__ wout,
                                                   float* __restrict__ out) {
    __shared__ float sw[10000];
    __shared__ float so[600];
    __shared__ float zs[100];
    const int b = blockIdx.x, tid = threadIdx.x;
    for (int i = tid; i < 10000; i += 128) sw[i] = wrec[i];
    for (int i = tid; i < 600; i += 128) so[i] = wout[i];
    if (tid < 100) zs[tid] = 0.f;
    float v = 0.f, ii = 0.f, vo = 0.f, io = 0.f;
    __syncthreads();

    for (int t = 0; t < 50; t++) {
        float zn = 0.f, inew = 0.f, vnew = 0.f;
        if (tid < 100) {
            float rec = 0.f;                       // recurrent uses OLD z
            for (int j = 0; j < 100; j++) rec += zs[j] * sw[tid * 100 + j];
            float vd = v + 0.1f * (ii - v);
            float id = 0.9f * ii;
            zn = (vd - 0.3f > 0.f) ? 1.f : 0.f;
            vnew = (1.f - zn) * vd;
            inew = id + g_xin[(t * 16 + b) * 100 + tid] + rec;
        }
        __syncthreads();
        if (tid < 100) { zs[tid] = zn; v = vnew; ii = inew; }
        __syncthreads();
        if (tid < 6) {
            float y = 0.f;
            for (int h = 0; h < 100; h++) y += zs[h] * so[tid * 100 + h];
            float von = vo + 0.1f * (io - vo);
            io = 0.8f * io + y;
            vo = von;
            out[(t * 16 + b) * 6 + tid] = von;
        }
        __syncthreads();
    }
}

extern "C" void kernel_launch(void* const* d_in, const int* in_sizes, int n_in,
                              void* d_out, int out_size) {
    const float *x = 0, *win = 0, *wrec = 0, *wout = 0;
    for (int i = 0; i < n_in; i++) {
        if (in_sizes[i] == 368640000) x = (const float*)d_in[i];
        else if (in_sizes[i] == 46080000) win = (const float*)d_in[i];
        else if (in_sizes[i] == 10000) wrec = (const float*)d_in[i];
        else if (in_sizes[i] == 600) wout = (const float*)d_in[i];
    }
    cudaFuncSetAttribute(gemm_s8, cudaFuncAttributeMaxDynamicSharedMemorySize, SMEM_TOTAL);
    wconv<<<NCHUNK, 128>>>(win);
    gemm_s8<<<dim3(NRT, SPLITS), NTHREADS, SMEM_TOTAL>>>(x);
    reduce_kernel<<<800, 128>>>();
    scan_kernel<<<16, 128>>>(wrec, wout, (float*)d_out);
}